// round 1
// baseline (speedup 1.0000x reference)
#include <cuda_runtime.h>
#include <math.h>

// Problem constants
#define Bn    4
#define Nn    2048
#define Hn    8
#define Dn    64
#define Fn    512
#define ROWS  (Bn * Nn)          // 8192
#define BH    (Bn * Hn)          // 32
#define SLOPE 0.2f

// Scratch (device globals; allocation is forbidden)
__device__ float g_Wh[Bn * Nn * Fn];    // 16 MB: leaky_relu(h @ W_r), flat == [B,H,N,d]
__device__ float g_er[BH * Nn];         // er[b,h,j]
__device__ float g_p [BH * Nn];         // exp(er - max)
__device__ float g_S [BH * Nn];         // row softmax denominators

// ---------------------------------------------------------------------------
// Kernel 1: Wh = leaky_relu(h @ W_r).  M=8192, K=512, Ncols=512.
// 64x64 block tile, 16 k-slab, 256 threads, 4x4 per thread.
// ---------------------------------------------------------------------------
__global__ void gemm_wh_kernel(const float* __restrict__ h,
                               const float* __restrict__ W) {
    __shared__ float As[16][64];   // [k][m] (transposed on fill)
    __shared__ float Bs[16][64];   // [k][n]

    const int m0 = blockIdx.x * 64;
    const int n0 = blockIdx.y * 64;
    const int t  = threadIdx.x;
    const int tx = t & 15, ty = t >> 4;

    const int ar = t >> 2;          // A-tile row (0..63)
    const int ac = (t & 3) * 4;     // A-tile k offset
    const int br = t >> 4;          // B-tile k row (0..15)
    const int bc = (t & 15) * 4;    // B-tile col offset

    float acc[4][4] = {};

    for (int k0 = 0; k0 < Fn; k0 += 16) {
        float4 av = *(const float4*)&h[(size_t)(m0 + ar) * Fn + k0 + ac];
        As[ac + 0][ar] = av.x;
        As[ac + 1][ar] = av.y;
        As[ac + 2][ar] = av.z;
        As[ac + 3][ar] = av.w;
        *(float4*)&Bs[br][bc] = *(const float4*)&W[(size_t)(k0 + br) * Fn + n0 + bc];
        __syncthreads();
#pragma unroll
        for (int k = 0; k < 16; k++) {
            float4 a4 = *(const float4*)&As[k][ty * 4];
            float4 b4 = *(const float4*)&Bs[k][tx * 4];
            float aa[4] = {a4.x, a4.y, a4.z, a4.w};
            float bb[4] = {b4.x, b4.y, b4.z, b4.w};
#pragma unroll
            for (int i = 0; i < 4; i++)
#pragma unroll
                for (int j = 0; j < 4; j++)
                    acc[i][j] += aa[i] * bb[j];
        }
        __syncthreads();
    }

#pragma unroll
    for (int i = 0; i < 4; i++) {
        const int m = m0 + ty * 4 + i;
#pragma unroll
        for (int j = 0; j < 4; j++) {
            const int n = n0 + tx * 4 + j;
            float v = acc[i][j];
            v = v > 0.f ? v : SLOPE * v;
            g_Wh[(size_t)m * Fn + n] = v;
        }
    }
}

// ---------------------------------------------------------------------------
// Kernel 2: er[row] = dot(Wh[row, 0:64], a).  One warp per row, 65536 rows.
// ---------------------------------------------------------------------------
__global__ void er_kernel(const float* __restrict__ a) {
    const int warp = (blockIdx.x * blockDim.x + threadIdx.x) >> 5;
    const int lane = threadIdx.x & 31;
    if (warp >= BH * Nn) return;
    const float* row = g_Wh + (size_t)warp * Dn;
    float s = row[lane] * a[lane] + row[lane + 32] * a[lane + 32];
#pragma unroll
    for (int o = 16; o; o >>= 1) s += __shfl_down_sync(0xffffffffu, s, o);
    if (lane == 0) g_er[warp] = s;
}

// ---------------------------------------------------------------------------
// Kernel 3: per (b,h): M = max_j er; p_j = exp(er_j - M).  32 blocks.
// ---------------------------------------------------------------------------
__global__ void maxexp_kernel() {
    __shared__ float sm[8];
    const int bh = blockIdx.x;
    const float* e = g_er + bh * Nn;
    float mx = -1e30f;
    for (int i = threadIdx.x; i < Nn; i += 256) mx = fmaxf(mx, e[i]);
#pragma unroll
    for (int o = 16; o; o >>= 1) mx = fmaxf(mx, __shfl_xor_sync(0xffffffffu, mx, o));
    if ((threadIdx.x & 31) == 0) sm[threadIdx.x >> 5] = mx;
    __syncthreads();
    float mall = sm[0];
#pragma unroll
    for (int i = 1; i < 8; i++) mall = fmaxf(mall, sm[i]);
    for (int i = threadIdx.x; i < Nn; i += 256)
        g_p[bh * Nn + i] = expf(e[i] - mall);
}

// ---------------------------------------------------------------------------
// Kernel 4: S[b,h,i] = sum_j adj[b,i,j] * p[b,h,j].  One warp per (b,i).
// ---------------------------------------------------------------------------
__global__ void s_kernel(const int* __restrict__ adj) {
    const int w    = (blockIdx.x * blockDim.x + threadIdx.x) >> 5;
    const int lane = threadIdx.x & 31;
    if (w >= ROWS) return;
    const int b = w >> 11;
    const int i = w & (Nn - 1);
    const int* arow = adj + (size_t)w * Nn;
    const float* pb = g_p + b * Hn * Nn;
    float s[Hn] = {};
    for (int j = lane; j < Nn; j += 32) {
        const float av = (float)arow[j];
#pragma unroll
        for (int hh = 0; hh < Hn; hh++) s[hh] += av * pb[hh * Nn + j];
    }
#pragma unroll
    for (int hh = 0; hh < Hn; hh++) {
        float v = s[hh];
#pragma unroll
        for (int o = 16; o; o >>= 1) v += __shfl_down_sync(0xffffffffu, v, o);
        if (lane == 0) g_S[b * Hn * Nn + hh * Nn + i] = v;
    }
}

// ---------------------------------------------------------------------------
// Kernel 5: out[b,h,i,:] = elu( (1/S[b,h,i]) * sum_j adj[b,i,j]*p[b,h,j]*Wh[b,h,j,:] )
// Dense GEMM per (b,h): [2048x2048] @ [2048x64].  64x64x16 tile.
// Output written at flat [B,H,N,d] offsets == d_out layout.
// ---------------------------------------------------------------------------
__global__ void att_kernel(const int* __restrict__ adj,
                           float* __restrict__ out) {
    __shared__ float As[16][64];   // [k][i]
    __shared__ float Bs[16][64];   // [k][c], p folded in

    const int b  = blockIdx.z;
    const int hh = blockIdx.y;
    const int i0 = blockIdx.x * 64;

    const int*   A   = adj  + (size_t)b * Nn * Nn;
    const float* Whb = g_Wh + (size_t)b * Hn * Nn * Dn + (size_t)hh * Nn * Dn;
    const float* pb  = g_p  + b * Hn * Nn + hh * Nn;
    const float* Sb  = g_S  + b * Hn * Nn + hh * Nn;

    const int t  = threadIdx.x;
    const int tx = t & 15, ty = t >> 4;
    const int ar = t >> 2;
    const int ac = (t & 3) * 4;
    const int br = t >> 4;
    const int bc = (t & 15) * 4;

    float acc[4][4] = {};

    for (int k0 = 0; k0 < Nn; k0 += 16) {
        int4 av = *(const int4*)&A[(size_t)(i0 + ar) * Nn + k0 + ac];
        As[ac + 0][ar] = (float)av.x;
        As[ac + 1][ar] = (float)av.y;
        As[ac + 2][ar] = (float)av.z;
        As[ac + 3][ar] = (float)av.w;
        const float pk = pb[k0 + br];
        float4 wv = *(const float4*)&Whb[(size_t)(k0 + br) * Dn + bc];
        Bs[br][bc + 0] = pk * wv.x;
        Bs[br][bc + 1] = pk * wv.y;
        Bs[br][bc + 2] = pk * wv.z;
        Bs[br][bc + 3] = pk * wv.w;
        __syncthreads();
#pragma unroll
        for (int k = 0; k < 16; k++) {
            float4 a4 = *(const float4*)&As[k][ty * 4];
            float4 b4 = *(const float4*)&Bs[k][tx * 4];
            float aa[4] = {a4.x, a4.y, a4.z, a4.w};
            float bb[4] = {b4.x, b4.y, b4.z, b4.w};
#pragma unroll
            for (int i = 0; i < 4; i++)
#pragma unroll
                for (int j = 0; j < 4; j++)
                    acc[i][j] += aa[i] * bb[j];
        }
        __syncthreads();
    }

#pragma unroll
    for (int i = 0; i < 4; i++) {
        const int irow = i0 + ty * 4 + i;
        float sden = Sb[irow];
        if (sden == 0.f) sden = 1.f;   // degenerate (no neighbors) guard
        const float inv = 1.f / sden;
#pragma unroll
        for (int j = 0; j < 4; j++) {
            const int c = tx * 4 + j;
            float v = acc[i][j] * inv;
            v = v > 0.f ? v : expm1f(v);
            out[(size_t)b * (Hn * Nn * Dn) + (size_t)hh * (Nn * Dn)
                + (size_t)irow * Dn + c] = v;
        }
    }
}

// ---------------------------------------------------------------------------
// Launch
// Inputs (metadata order): 0=h [4,2048,512] f32, 1=adj [4,2048,2048] i32,
//                          2=W_l (UNUSED — cancels in softmax), 3=W_r, 4=a [64,1]
// ---------------------------------------------------------------------------
extern "C" void kernel_launch(void* const* d_in, const int* in_sizes, int n_in,
                              void* d_out, int out_size) {
    const float* h   = (const float*)d_in[0];
    const int*   adj = (const int*)  d_in[1];
    const float* W_r = (const float*)d_in[3];
    const float* a   = (const float*)d_in[4];
    float* out = (float*)d_out;

    // 1. Wh = leaky_relu(h @ W_r)
    {
        dim3 grid(ROWS / 64, Fn / 64);
        gemm_wh_kernel<<<grid, 256>>>(h, W_r);
    }
    // 2. er = Wh_rows . a   (65536 warps)
    {
        const int warps = BH * Nn;
        er_kernel<<<(warps * 32 + 255) / 256, 256>>>(a);
    }
    // 3. p = exp(er - max)
    maxexp_kernel<<<BH, 256>>>();
    // 4. S = Adj @ p  (per head)
    s_kernel<<<(ROWS * 32 + 255) / 256, 256>>>(adj);
    // 5. out = elu(D^-1 Adj @ (p .* Wh))
    {
        dim3 grid(Nn / 64, Hn, Bn);
        att_kernel<<<grid, 256>>>(adj, out);
    }
}

// round 3
// speedup vs baseline: 2.2126x; 2.2126x over previous
#include <cuda_runtime.h>
#include <cuda_bf16.h>
#include <math.h>
#include <stdint.h>

// Problem constants
#define Bn    4
#define Nn    2048
#define Hn    8
#define Dn    64
#define Fn    512
#define ROWS  (Bn * Nn)          // 8192
#define BH    (Bn * Hn)          // 32
#define SLOPE 0.2f

// Scratch (device globals; allocation is forbidden)
__device__ float g_Wh[Bn * Nn * Fn];                    // leaky_relu(h @ W_r)
__device__ float g_er[BH * Nn];
__device__ float g_p [BH * Nn];
__device__ float g_S [BH * Nn];
__device__ __nv_bfloat16 g_adjb[(size_t)Bn * Nn * Nn];  // adj as bf16 (exact)
__device__ __nv_bfloat16 g_Bhi[(size_t)Bn * Fn * Nn];   // K-major hi limb of p*Wh
__device__ __nv_bfloat16 g_Blo[(size_t)Bn * Fn * Nn];   // K-major lo limb

// ---------------------------------------------------------------------------
// Portable PTX helpers (valid on compute_103: no tcgen05)
// ---------------------------------------------------------------------------
__device__ __forceinline__ uint32_t smem_u32(const void* p) {
    uint32_t a;
    asm("{ .reg .u64 t; cvta.to.shared.u64 t, %1; cvt.u32.u64 %0, t; }"
        : "=r"(a) : "l"(p));
    return a;
}
#define SWZ(x) ((x) ^ (((x) >> 3) & 0x70))

#define CP_ASYNC16(dst, src) \
    asm volatile("cp.async.cg.shared.global [%0], [%1], 16;" \
                 :: "r"(dst), "l"(src) : "memory")
#define CP_COMMIT() asm volatile("cp.async.commit_group;" ::: "memory")
#define CP_WAIT(n)  asm volatile("cp.async.wait_group %0;" :: "n"(n) : "memory")

__device__ __forceinline__ void ldsm_x4(uint32_t* r, uint32_t addr) {
    asm volatile("ldmatrix.sync.aligned.m8n8.x4.shared.b16 {%0,%1,%2,%3}, [%4];"
                 : "=r"(r[0]), "=r"(r[1]), "=r"(r[2]), "=r"(r[3]) : "r"(addr));
}

__device__ __forceinline__ void mma16816(float* d, const uint32_t* a,
                                         uint32_t b0, uint32_t b1) {
    asm volatile(
        "mma.sync.aligned.m16n8k16.row.col.f32.bf16.bf16.f32 "
        "{%0,%1,%2,%3}, {%4,%5,%6,%7}, {%8,%9}, {%0,%1,%2,%3};"
        : "+f"(d[0]), "+f"(d[1]), "+f"(d[2]), "+f"(d[3])
        : "r"(a[0]), "r"(a[1]), "r"(a[2]), "r"(a[3]), "r"(b0), "r"(b1));
}

// ---------------------------------------------------------------------------
// Kernel 1: Wh = leaky_relu(h @ W_r).  fp32 SIMT (tensorize next round).
// ---------------------------------------------------------------------------
__global__ void gemm_wh_kernel(const float* __restrict__ h,
                               const float* __restrict__ W) {
    __shared__ float As[16][64];
    __shared__ float Bs[16][64];

    const int m0 = blockIdx.x * 64;
    const int n0 = blockIdx.y * 64;
    const int t  = threadIdx.x;
    const int tx = t & 15, ty = t >> 4;
    const int ar = t >> 2;
    const int ac = (t & 3) * 4;
    const int br = t >> 4;
    const int bc = (t & 15) * 4;

    float acc[4][4] = {};

    for (int k0 = 0; k0 < Fn; k0 += 16) {
        float4 av = *(const float4*)&h[(size_t)(m0 + ar) * Fn + k0 + ac];
        As[ac + 0][ar] = av.x;
        As[ac + 1][ar] = av.y;
        As[ac + 2][ar] = av.z;
        As[ac + 3][ar] = av.w;
        *(float4*)&Bs[br][bc] = *(const float4*)&W[(size_t)(k0 + br) * Fn + n0 + bc];
        __syncthreads();
#pragma unroll
        for (int k = 0; k < 16; k++) {
            float4 a4 = *(const float4*)&As[k][ty * 4];
            float4 b4 = *(const float4*)&Bs[k][tx * 4];
            float aa[4] = {a4.x, a4.y, a4.z, a4.w};
            float bb[4] = {b4.x, b4.y, b4.z, b4.w};
#pragma unroll
            for (int i = 0; i < 4; i++)
#pragma unroll
                for (int j = 0; j < 4; j++)
                    acc[i][j] += aa[i] * bb[j];
        }
        __syncthreads();
    }

#pragma unroll
    for (int i = 0; i < 4; i++) {
        const int m = m0 + ty * 4 + i;
#pragma unroll
        for (int j = 0; j < 4; j++) {
            const int n = n0 + tx * 4 + j;
            float v = acc[i][j];
            v = v > 0.f ? v : SLOPE * v;
            g_Wh[(size_t)m * Fn + n] = v;
        }
    }
}

// ---------------------------------------------------------------------------
// Kernel 2: er[row] = dot(Wh[row, 0:64], a)
// ---------------------------------------------------------------------------
__global__ void er_kernel(const float* __restrict__ a) {
    const int warp = (blockIdx.x * blockDim.x + threadIdx.x) >> 5;
    const int lane = threadIdx.x & 31;
    if (warp >= BH * Nn) return;
    const float* row = g_Wh + (size_t)warp * Dn;
    float s = row[lane] * a[lane] + row[lane + 32] * a[lane + 32];
#pragma unroll
    for (int o = 16; o; o >>= 1) s += __shfl_down_sync(0xffffffffu, s, o);
    if (lane == 0) g_er[warp] = s;
}

// ---------------------------------------------------------------------------
// Kernel 3: p = exp(er - rowmax) per (b,h)
// ---------------------------------------------------------------------------
__global__ void maxexp_kernel() {
    __shared__ float sm[8];
    const int bh = blockIdx.x;
    const float* e = g_er + bh * Nn;
    float mx = -1e30f;
    for (int i = threadIdx.x; i < Nn; i += 256) mx = fmaxf(mx, e[i]);
#pragma unroll
    for (int o = 16; o; o >>= 1) mx = fmaxf(mx, __shfl_xor_sync(0xffffffffu, mx, o));
    if ((threadIdx.x & 31) == 0) sm[threadIdx.x >> 5] = mx;
    __syncthreads();
    float mall = sm[0];
#pragma unroll
    for (int i = 1; i < 8; i++) mall = fmaxf(mall, sm[i]);
    for (int i = threadIdx.x; i < Nn; i += 256)
        g_p[bh * Nn + i] = expf(e[i] - mall);
}

// ---------------------------------------------------------------------------
// Kernel 4: S[b,h,i] = sum_j adj[b,i,j] * p[b,h,j]
// ---------------------------------------------------------------------------
__global__ void s_kernel(const int* __restrict__ adj) {
    const int w    = (blockIdx.x * blockDim.x + threadIdx.x) >> 5;
    const int lane = threadIdx.x & 31;
    if (w >= ROWS) return;
    const int b = w >> 11;
    const int i = w & (Nn - 1);
    const int* arow = adj + (size_t)w * Nn;
    const float* pb = g_p + b * Hn * Nn;
    float s[Hn] = {};
    for (int j = lane; j < Nn; j += 32) {
        const float av = (float)arow[j];
#pragma unroll
        for (int hh = 0; hh < Hn; hh++) s[hh] += av * pb[hh * Nn + j];
    }
#pragma unroll
    for (int hh = 0; hh < Hn; hh++) {
        float v = s[hh];
#pragma unroll
        for (int o = 16; o; o >>= 1) v += __shfl_down_sync(0xffffffffu, v, o);
        if (lane == 0) g_S[b * Hn * Nn + hh * Nn + i] = v;
    }
}

// ---------------------------------------------------------------------------
// Kernel 4a: adj int32 -> bf16 (exact for {0,1}).  8 elems/thread.
// ---------------------------------------------------------------------------
__global__ void adjconv_kernel(const int* __restrict__ adj) {
    const size_t idx = (size_t)(blockIdx.x * blockDim.x + threadIdx.x) * 8;
    int4 v0 = *(const int4*)&adj[idx];
    int4 v1 = *(const int4*)&adj[idx + 4];
    __nv_bfloat162 r0 = __floats2bfloat162_rn((float)v0.x, (float)v0.y);
    __nv_bfloat162 r1 = __floats2bfloat162_rn((float)v0.z, (float)v0.w);
    __nv_bfloat162 r2 = __floats2bfloat162_rn((float)v1.x, (float)v1.y);
    __nv_bfloat162 r3 = __floats2bfloat162_rn((float)v1.z, (float)v1.w);
    uint4 u;
    u.x = *(uint32_t*)&r0; u.y = *(uint32_t*)&r1;
    u.z = *(uint32_t*)&r2; u.w = *(uint32_t*)&r3;
    *(uint4*)&g_adjb[idx] = u;
}

// ---------------------------------------------------------------------------
// Kernel 4b: build K-major bf16 hi/lo B operand: [b][col=h*64+c][j] = p[j]*Wh[j,c]
// ---------------------------------------------------------------------------
__global__ void bprep_kernel() {
    __shared__ float ts[64][65];
    const int j0 = blockIdx.x * 64;
    const int h  = blockIdx.y;
    const int b  = blockIdx.z;
    const int t  = threadIdx.x;   // 256 threads

    const float* Wb = g_Wh + (size_t)(b * Hn + h) * Nn * Dn;
    const float* pb = g_p + (b * Hn + h) * Nn;

#pragma unroll
    for (int it = 0; it < 16; it++) {
        int idx = it * 256 + t;
        int r = idx >> 6, c = idx & 63;
        ts[r][c] = Wb[(size_t)(j0 + r) * Dn + c] * pb[j0 + r];
    }
    __syncthreads();

    __nv_bfloat16* bh = g_Bhi + ((size_t)b * Fn + h * Dn) * Nn;
    __nv_bfloat16* bl = g_Blo + ((size_t)b * Fn + h * Dn) * Nn;
#pragma unroll
    for (int it = 0; it < 16; it++) {
        int idx = it * 256 + t;
        int c = idx >> 6, r = idx & 63;
        float x = ts[r][c];
        __nv_bfloat16 hi = __float2bfloat16(x);
        float lo = x - __bfloat162float(hi);
        bh[(size_t)c * Nn + j0 + r] = hi;
        bl[(size_t)c * Nn + j0 + r] = __float2bfloat16(lo);
    }
}

// ---------------------------------------------------------------------------
// Kernel 5: warp-MMA attention GEMM (HMMA.16816.bf16, fp32 accum).
// CTA: C[128 x 128] = adjb[i0:i0+128, :] @ B[n0:n0+128, :]^T   (K = 2048)
// 8 warps (2M x 4N); warp tile 64x32; BK=64; 2-stage cp.async pipeline.
// Epilogue: * 1/S, elu, store to [B,H,N,d]-flat out.
// SMEM/stage: A 16KB | Bhi 16KB | Blo 16KB  (SW128-swizzled, 128B rows)
// ---------------------------------------------------------------------------
#define STG_BYTES 49152
#define ATT_SMEM  (2 * STG_BYTES)
#define OFF_A  0
#define OFF_BH 16384
#define OFF_BL 32768

__global__ void __launch_bounds__(256) att_mma_kernel(float* __restrict__ out) {
    extern __shared__ __align__(1024) char smem[];
    const uint32_t sb = smem_u32(smem);

    const int t    = threadIdx.x;
    const int wid  = t >> 5, lane = t & 31;
    const int i0   = blockIdx.x * 128;   // output rows
    const int n0c  = blockIdx.y * 128;   // output cols (of 512)
    const int b    = blockIdx.z;

    const __nv_bfloat16* gA  = g_adjb + ((size_t)b * Nn + i0) * Nn;
    const __nv_bfloat16* gBh = g_Bhi + ((size_t)b * Fn + n0c) * Nn;
    const __nv_bfloat16* gBl = g_Blo + ((size_t)b * Fn + n0c) * Nn;

    // cp.async indices: chunk c in [0,1024): row = c>>3 (128 rows), chk = c&7
    const int c_row = t >> 1;            // rows t/2 (two threads per row? no:)
    // simpler: per it, c = it*256 + t
    auto load_stage = [&](int slab, int stg) {
        const int k0 = slab * 64;
        const uint32_t base = sb + stg * STG_BYTES;
#pragma unroll
        for (int it = 0; it < 4; it++) {
            int c = it * 256 + t;
            int row = c >> 3, chk = c & 7;
            uint32_t doff = SWZ((uint32_t)(row * 128 + chk * 16));
            CP_ASYNC16(base + OFF_A + doff, gA + (size_t)row * Nn + k0 + chk * 8);
            CP_ASYNC16(base + OFF_BH + doff, gBh + (size_t)row * Nn + k0 + chk * 8);
            CP_ASYNC16(base + OFF_BL + doff, gBl + (size_t)row * Nn + k0 + chk * 8);
        }
    };
    (void)c_row;

    // warp / lane geometry
    const int wm = wid & 1, wn = wid >> 1;
    const int g  = lane >> 2, tg = lane & 3;
    const int lrow = (lane & 7) + ((lane >> 3) & 1) * 8;  // 0..15
    const int lkb  = (lane >> 4) * 16;                    // 0 or 16 bytes

    uint32_t a_off[4], b_off[2];
#pragma unroll
    for (int mt = 0; mt < 4; mt++)
        a_off[mt] = (uint32_t)((wm * 64 + mt * 16 + lrow) * 128 + lkb);
#pragma unroll
    for (int nt2 = 0; nt2 < 2; nt2++)
        b_off[nt2] = (uint32_t)((wn * 32 + nt2 * 16 + lrow) * 128 + lkb);

    float acc[4][4][4];
#pragma unroll
    for (int i = 0; i < 4; i++)
#pragma unroll
        for (int j = 0; j < 4; j++)
#pragma unroll
            for (int k = 0; k < 4; k++) acc[i][j][k] = 0.f;

    load_stage(0, 0);
    CP_COMMIT();

    const int NSLAB = Nn / 64;  // 32
    for (int s = 0; s < NSLAB; s++) {
        const int stg = s & 1;
        if (s + 1 < NSLAB) {
            load_stage(s + 1, stg ^ 1);
            CP_COMMIT();
            CP_WAIT(1);
        } else {
            CP_WAIT(0);
        }
        __syncthreads();

        const uint32_t Ab = sb + stg * STG_BYTES + OFF_A;
        const uint32_t Bh = sb + stg * STG_BYTES + OFF_BH;
        const uint32_t Bl = sb + stg * STG_BYTES + OFF_BL;

#pragma unroll
        for (int kk = 0; kk < 4; kk++) {
            uint32_t af[4][4], bhf[2][4], blf[2][4];
#pragma unroll
            for (int mt = 0; mt < 4; mt++)
                ldsm_x4(af[mt], Ab + SWZ(a_off[mt] + kk * 32));
#pragma unroll
            for (int nt2 = 0; nt2 < 2; nt2++) {
                ldsm_x4(bhf[nt2], Bh + SWZ(b_off[nt2] + kk * 32));
                ldsm_x4(blf[nt2], Bl + SWZ(b_off[nt2] + kk * 32));
            }
#pragma unroll
            for (int mt = 0; mt < 4; mt++)
#pragma unroll
                for (int nt = 0; nt < 4; nt++) {
                    const int n2 = nt >> 1, hf = nt & 1;
                    mma16816(acc[mt][nt], af[mt], bhf[n2][hf], bhf[n2][hf + 2]);
                    mma16816(acc[mt][nt], af[mt], blf[n2][hf], blf[n2][hf + 2]);
                }
        }
        __syncthreads();
    }

    // Epilogue.  Warp's 32 cols lie inside one head.
    const int hwarp = (n0c + wn * 32) >> 6;
    const int cbase = ((wn * 32) & 63) + tg * 2;
    const float* Sb = g_S + (size_t)(b * Hn + hwarp) * Nn;
    float* ob = out + (size_t)(b * Hn + hwarp) * Nn * Dn;

#pragma unroll
    for (int mt = 0; mt < 4; mt++) {
        const int r0 = i0 + wm * 64 + mt * 16 + g;
        const int r1 = r0 + 8;
        float s0 = Sb[r0]; if (s0 == 0.f) s0 = 1.f;
        float s1 = Sb[r1]; if (s1 == 0.f) s1 = 1.f;
        const float inv0 = 1.f / s0, inv1 = 1.f / s1;
#pragma unroll
        for (int nt = 0; nt < 4; nt++) {
            const int c = cbase + nt * 8;
            float x0 = acc[mt][nt][0] * inv0;
            float x1 = acc[mt][nt][1] * inv0;
            float x2 = acc[mt][nt][2] * inv1;
            float x3 = acc[mt][nt][3] * inv1;
            float2 v0, v1;
            v0.x = x0 > 0.f ? x0 : expm1f(x0);
            v0.y = x1 > 0.f ? x1 : expm1f(x1);
            v1.x = x2 > 0.f ? x2 : expm1f(x2);
            v1.y = x3 > 0.f ? x3 : expm1f(x3);
            *(float2*)&ob[(size_t)r0 * Dn + c] = v0;
            *(float2*)&ob[(size_t)r1 * Dn + c] = v1;
        }
    }
}

// ---------------------------------------------------------------------------
// Launch.  Inputs: 0=h f32, 1=adj i32, 2=W_l (unused), 3=W_r f32, 4=a f32
// ---------------------------------------------------------------------------
extern "C" void kernel_launch(void* const* d_in, const int* in_sizes, int n_in,
                              void* d_out, int out_size) {
    const float* h   = (const float*)d_in[0];
    const int*   adj = (const int*)  d_in[1];
    const float* W_r = (const float*)d_in[3];
    const float* a   = (const float*)d_in[4];
    float* out = (float*)d_out;

    static int smem_set = 0;
    if (!smem_set) {
        cudaFuncSetAttribute(att_mma_kernel,
                             cudaFuncAttributeMaxDynamicSharedMemorySize, ATT_SMEM);
        smem_set = 1;
    }

    // 1. Wh = leaky_relu(h @ W_r)
    {
        dim3 grid(ROWS / 64, Fn / 64);
        gemm_wh_kernel<<<grid, 256>>>(h, W_r);
    }
    // 2. er = Wh_rows . a
    {
        const int warps = BH * Nn;
        er_kernel<<<(warps * 32 + 255) / 256, 256>>>(a);
    }
    // 3. p = exp(er - max)
    maxexp_kernel<<<BH, 256>>>();
    // 4. S = Adj @ p
    s_kernel<<<(ROWS * 32 + 255) / 256, 256>>>(adj);
    // 4a. adj -> bf16
    {
        const size_t total = (size_t)Bn * Nn * Nn / 8;   // 8 elems/thread
        adjconv_kernel<<<(unsigned)(total / 256), 256>>>(adj);
    }
    // 4b. B operand hi/lo
    {
        dim3 grid(Nn / 64, Hn, Bn);
        bprep_kernel<<<grid, 256>>>();
    }
    // 5. out = elu(D^-1 Adj @ (p .* Wh))  — HMMA tensor cores
    {
        dim3 grid(Nn / 128, Fn / 128, Bn);
        att_mma_kernel<<<grid, 256, ATT_SMEM>>>(out);
    }
}